// round 11
// baseline (speedup 1.0000x reference)
#include <cuda_runtime.h>

// FFF (fast feedforward) sparse tree-walk, round 11: warp-specialized
// producer/consumer. Inputs (metadata order):
//   d_in[0]: oldx  [8192, 768]  float32
//   d_in[1]: w_in  [4095, 768]  float32
//   d_in[2]: w_out [768, 4095]  float32
// Output: [8192, 768] float32
//
//   k1: transpose w_out -> node-major scratch
//   k2: walk — per block: 4 decide warps (serial tree walk, stall-heavy)
//       + 4 accum warps (L1-streaming w_out accumulation), overlapped via a
//       2-slot smem ring per warp pair. Complementary pipe usage hides the
//       decide chain's scoreboard stalls under accum's load stream.

#define FFF_B       8192
#define FFF_D       768
#define FFF_NODES   4095
#define FFF_DEPTH   11
#define FFF_LEVELS  (FFF_DEPTH + 1)      // 12 nodes on the path
#define FFF_ROW4    (FFF_D / 4)          // 192 float4 per 768-float row

#define PAIRS       4                    // producer/consumer warp pairs per block
#define T_TOK       4                    // tokens per pair
#define WALK_BLOCKS (FFF_B / (PAIRS * T_TOK))   // 512

// Transposed w_out scratch: [FFF_NODES, FFF_D] (node-major, coalesced rows).
__device__ float g_wout_t[(size_t)FFF_NODES * FFF_D];

// ---------------------------------------------------------------------------
// k1: tiled transpose w_out [768, 4095] -> g_wout_t [4095, 768]
// ---------------------------------------------------------------------------
__global__ void fff_transpose_wout(const float* __restrict__ w_out) {
    __shared__ float tile[32][33];
    const int n0 = blockIdx.x * 32;   // node dim (4095)
    const int o0 = blockIdx.y * 32;   // output dim (768)

    const int n = n0 + threadIdx.x;
    #pragma unroll
    for (int j = 0; j < 4; j++) {
        const int o = o0 + threadIdx.y + j * 8;     // o < 768 always
        if (n < FFF_NODES) {
            tile[threadIdx.y + j * 8][threadIdx.x] = w_out[(size_t)o * FFF_NODES + n];
        }
    }
    __syncthreads();

    const int oo = o0 + threadIdx.x;                // always < 768
    #pragma unroll
    for (int j = 0; j < 4; j++) {
        const int nn = n0 + threadIdx.y + j * 8;
        if (nn < FFF_NODES) {
            g_wout_t[(size_t)nn * FFF_D + oo] = tile[threadIdx.x][threadIdx.y + j * 8];
        }
    }
}

__device__ __forceinline__ float fff_warp_sum(float v) {
    #pragma unroll
    for (int off = 16; off > 0; off >>= 1)
        v += __shfl_xor_sync(0xffffffffu, v, off);
    return v;
}

// ---------------------------------------------------------------------------
// k2: warp-specialized walk. Warps 0-3 = decide (producers), 4-7 = accum
// (consumers). Pair p moves tokens [base, base+T_TOK) through a 2-slot ring.
// ---------------------------------------------------------------------------
__global__ void __launch_bounds__(256, 4)
fff_walk_ws_kernel(const float* __restrict__ x,
                   const float* __restrict__ w_in,
                   float* __restrict__ out) {
    __shared__ float    s_acts[PAIRS][2][FFF_LEVELS];
    __shared__ unsigned s_leaf[PAIRS][2];
    __shared__ int      s_flag[PAIRS * 2];          // 0 = empty, 1 = full

    const int tid  = (int)threadIdx.x;
    const int warp = tid >> 5;
    const int lane = tid & 31;
    const int p    = warp & 3;                      // pair index
    const int base = ((int)blockIdx.x * PAIRS + p) * T_TOK;

    if (tid < PAIRS * 2) s_flag[tid] = 0;
    __syncthreads();

    volatile int* flags = s_flag;

    if (warp < 4) {
        // =================== decide (producer) ===================
        const float4* __restrict__ wi4 = reinterpret_cast<const float4*>(w_in);

        for (int j = 0; j < T_TOK; j++) {
            const int tok = base + j;
            const int s   = j & 1;

            // Backpressure: wait until slot consumed (initially empty).
            if (lane == 0) {
                while (flags[p * 2 + s] != 0) __nanosleep(32);
            }
            __syncwarp();

            const float4* __restrict__ x4 =
                reinterpret_cast<const float4*>(x) + (size_t)tok * FFF_ROW4;
            float4 xv[6];
            #pragma unroll
            for (int i = 0; i < 6; i++) xv[i] = x4[i * 32 + lane];

            float mylogit = 0.f;   // lane d holds the level-d logit
            unsigned cur = 0;
            #pragma unroll
            for (int d = 0; d < FFF_LEVELS; d++) {
                const float4* __restrict__ wr = wi4 + (size_t)cur * FFF_ROW4;
                float p0 = 0.f, p1 = 0.f, p2 = 0.f, p3 = 0.f;
                #pragma unroll
                for (int i = 0; i < 6; i += 2) {
                    const float4 a = wr[i * 32 + lane];
                    const float4 b = wr[(i + 1) * 32 + lane];
                    p0 = fmaf(a.x, xv[i].x, p0);
                    p1 = fmaf(a.y, xv[i].y, p1);
                    p2 = fmaf(a.z, xv[i].z, p2);
                    p3 = fmaf(a.w, xv[i].w, p3);
                    p0 = fmaf(b.x, xv[i + 1].x, p0);
                    p1 = fmaf(b.y, xv[i + 1].y, p1);
                    p2 = fmaf(b.z, xv[i + 1].z, p2);
                    p3 = fmaf(b.w, xv[i + 1].w, p3);
                }
                const float pv = fff_warp_sum((p0 + p1) + (p2 + p3));
                if (lane == d) mylogit = pv;
                cur = 2u * cur + 1u + (pv > 0.0f ? 1u : 0u);
            }

            // ONE exact-erf gelu (matches jax.nn.gelu approximate=False).
            const float myact = 0.5f * mylogit *
                                (1.0f + erff(mylogit * 0.70710678118654752440f));

            if (lane < FFF_LEVELS) s_acts[p][s][lane] = myact;
            if (lane == 0)         s_leaf[p][s] = cur + 1u;
            __threadfence_block();
            __syncwarp();
            if (lane == 0) flags[p * 2 + s] = 1;     // publish
        }
    } else {
        // =================== accum (consumer) ===================
        const float4* __restrict__ wo4 = reinterpret_cast<const float4*>(g_wout_t);

        for (int j = 0; j < T_TOK; j++) {
            const int tok = base + j;
            const int s   = j & 1;

            // Wait for producer.
            while (flags[p * 2 + s] == 0) __nanosleep(32);
            __threadfence_block();

            const unsigned vf = s_leaf[p][s];
            float acts[FFF_LEVELS];
            #pragma unroll
            for (int d = 0; d < FFF_LEVELS; d++) acts[d] = s_acts[p][s][d];
            __syncwarp();
            if (lane == 0) flags[p * 2 + s] = 0;     // release slot

            unsigned offs[FFF_LEVELS];
            #pragma unroll
            for (int d = 0; d < FFF_LEVELS; d++)
                offs[d] = ((vf >> (FFF_LEVELS - d)) - 1u) * (unsigned)FFF_ROW4;

            float4* __restrict__ o4 =
                reinterpret_cast<float4*>(out) + (size_t)tok * FFF_ROW4;
            #pragma unroll
            for (int i = 0; i < 6; i++) {
                const unsigned chunk = (unsigned)(i * 32 + lane);
                float a0 = 0.f, a1 = 0.f, a2 = 0.f, a3 = 0.f;
                #pragma unroll
                for (int d = 0; d < FFF_LEVELS; d++) {
                    const float4 w = wo4[offs[d] + chunk];   // 12 independent gathers
                    a0 = fmaf(acts[d], w.x, a0);
                    a1 = fmaf(acts[d], w.y, a1);
                    a2 = fmaf(acts[d], w.z, a2);
                    a3 = fmaf(acts[d], w.w, a3);
                }
                o4[chunk] = make_float4(a0, a1, a2, a3);
            }
        }
    }
}

extern "C" void kernel_launch(void* const* d_in, const int* in_sizes, int n_in,
                              void* d_out, int out_size) {
    const float* x     = (const float*)d_in[0];
    const float* w_in  = (const float*)d_in[1];
    const float* w_out = (const float*)d_in[2];
    float* out = (float*)d_out;

    // k1: transpose w_out into node-major scratch (accum depends on it).
    {
        dim3 block(32, 8);
        dim3 grid((FFF_NODES + 31) / 32, FFF_D / 32);
        fff_transpose_wout<<<grid, block>>>(w_out);
    }

    // k2: warp-specialized decide+accum, 16 tokens per 256-thread block.
    {
        fff_walk_ws_kernel<<<WALK_BLOCKS, 256>>>(x, w_in, out);
    }
}

// round 13
// speedup vs baseline: 1.0640x; 1.0640x over previous
#include <cuda_runtime.h>

// FFF (fast feedforward) sparse tree-walk, round 13 (R12 resubmit — infra fail).
// Inputs (metadata order):
//   d_in[0]: oldx  [8192, 768]  float32
//   d_in[1]: w_in  [4095, 768]  float32
//   d_in[2]: w_out [768, 4095]  float32
// Output: [8192, 768] float32
//
// Diagnosis: all prior variants pinned at ~40-53us = L2 bandwidth roofline
// (decide + accum each logically re-read ~300MB/iter through L2; L1 thrashes
// because every SM touches all 6 column-chunks of the hot upper-level rows).
//
//   k1: transpose w_out -> node-major scratch.
//   k2: decide (proven R8 kernel) -> acts[12] + leaf per token.
//   k3: accum, COLUMN-CHUNK PARTITIONED: each warp owns one fixed 512B chunk
//       of the 768-float row space and streams tokens. Per-SM hot footprint
//       for tree levels 0-7 drops to 255*512B = 128KB/group (L1-resident), so
//       only the deepest levels miss to L2. Accum L2 traffic ~150MB -> ~25MB.

#define FFF_B       8192
#define FFF_D       768
#define FFF_NODES   4095
#define FFF_DEPTH   11
#define FFF_LEVELS  (FFF_DEPTH + 1)      // 12 nodes on the path
#define FFF_ROW4    (FFF_D / 4)          // 192 float4 per 768-float row

#define ACC_GROUPS  6                    // 6 x 512B column chunks
#define ACC_BLOCKS_PER_GROUP 64
#define ACC_TOK_PER_WARP 16              // 64 blk * 8 warps * 16 = 8192 tokens

// Scratch: transposed w_out (node-major), per-token activations + leaf.
__device__ float    g_wout_t[(size_t)FFF_NODES * FFF_D];
__device__ float    g_acts[(size_t)FFF_B * FFF_LEVELS];
__device__ unsigned g_leaf[FFF_B];

// ---------------------------------------------------------------------------
// k1: tiled transpose w_out [768, 4095] -> g_wout_t [4095, 768]
// ---------------------------------------------------------------------------
__global__ void fff_transpose_wout(const float* __restrict__ w_out) {
    __shared__ float tile[32][33];
    const int n0 = blockIdx.x * 32;   // node dim (4095)
    const int o0 = blockIdx.y * 32;   // output dim (768)

    const int n = n0 + threadIdx.x;
    #pragma unroll
    for (int j = 0; j < 4; j++) {
        const int o = o0 + threadIdx.y + j * 8;     // o < 768 always
        if (n < FFF_NODES) {
            tile[threadIdx.y + j * 8][threadIdx.x] = w_out[(size_t)o * FFF_NODES + n];
        }
    }
    __syncthreads();

    const int oo = o0 + threadIdx.x;                // always < 768
    #pragma unroll
    for (int j = 0; j < 4; j++) {
        const int nn = n0 + threadIdx.y + j * 8;
        if (nn < FFF_NODES) {
            g_wout_t[(size_t)nn * FFF_D + oo] = tile[threadIdx.x][threadIdx.y + j * 8];
        }
    }
}

__device__ __forceinline__ float fff_warp_sum(float v) {
    #pragma unroll
    for (int off = 16; off > 0; off >>= 1)
        v += __shfl_xor_sync(0xffffffffu, v, off);
    return v;
}

// ---------------------------------------------------------------------------
// k2: decide — one warp per token (proven R8 kernel, 64 regs).
// ---------------------------------------------------------------------------
__global__ void __launch_bounds__(256, 4)
fff_decide_kernel(const float* __restrict__ x,
                  const float* __restrict__ w_in) {
    const int warp = (int)((blockIdx.x * blockDim.x + threadIdx.x) >> 5);
    const int lane = threadIdx.x & 31;

    const float4* __restrict__ x4  = reinterpret_cast<const float4*>(x) + (size_t)warp * FFF_ROW4;
    const float4* __restrict__ wi4 = reinterpret_cast<const float4*>(w_in);

    float4 xv[6];
    #pragma unroll
    for (int i = 0; i < 6; i++) xv[i] = x4[i * 32 + lane];

    float mylogit = 0.f;   // lane d holds the level-d logit
    unsigned cur = 0;
    #pragma unroll
    for (int d = 0; d < FFF_LEVELS; d++) {
        const float4* __restrict__ wr = wi4 + (size_t)cur * FFF_ROW4;
        float p0 = 0.f, p1 = 0.f, p2 = 0.f, p3 = 0.f;
        #pragma unroll
        for (int i = 0; i < 6; i += 2) {
            const float4 a = wr[i * 32 + lane];
            const float4 b = wr[(i + 1) * 32 + lane];
            p0 = fmaf(a.x, xv[i].x, p0);
            p1 = fmaf(a.y, xv[i].y, p1);
            p2 = fmaf(a.z, xv[i].z, p2);
            p3 = fmaf(a.w, xv[i].w, p3);
            p0 = fmaf(b.x, xv[i + 1].x, p0);
            p1 = fmaf(b.y, xv[i + 1].y, p1);
            p2 = fmaf(b.z, xv[i + 1].z, p2);
            p3 = fmaf(b.w, xv[i + 1].w, p3);
        }
        const float p = fff_warp_sum((p0 + p1) + (p2 + p3));
        if (lane == d) mylogit = p;
        cur = 2u * cur + 1u + (p > 0.0f ? 1u : 0u);
    }

    // ONE exact-erf gelu (matches jax.nn.gelu approximate=False); lane d -> act d.
    const float myact = 0.5f * mylogit *
                        (1.0f + erff(mylogit * 0.70710678118654752440f));

    if (lane < FFF_LEVELS) g_acts[(size_t)warp * FFF_LEVELS + lane] = myact;
    if (lane == 0)         g_leaf[warp] = cur + 1u;   // level-12 virtual node + 1
}

// ---------------------------------------------------------------------------
// k3: accum, column-chunk partitioned. Warp owns float4-chunk g*32+lane and
// streams 16 sequential tokens: 12 gathered LDG.128 + 1 STG.128 per token.
// Hot upper-level rows' 512B slices stay L1-resident on the owning SM.
// ---------------------------------------------------------------------------
__global__ void __launch_bounds__(256, 8)
fff_accum_chunked(float* __restrict__ out) {
    const int lane  = (int)threadIdx.x & 31;
    const int w     = (int)threadIdx.x >> 5;
    const int g     = (int)blockIdx.x / ACC_BLOCKS_PER_GROUP;   // chunk group 0..5
    const int b     = (int)blockIdx.x % ACC_BLOCKS_PER_GROUP;
    const unsigned chunk = (unsigned)(g * 32 + lane);           // float4 index in row
    const int wslot = b * 8 + w;                                // 0..511

    const float4* __restrict__ wo4 = reinterpret_cast<const float4*>(g_wout_t);

    #pragma unroll 2
    for (int k = 0; k < ACC_TOK_PER_WARP; k++) {
        const int tok = wslot * ACC_TOK_PER_WARP + k;

        const unsigned vf = g_leaf[tok];
        const float* __restrict__ ap = g_acts + (size_t)tok * FFF_LEVELS;

        float a0 = 0.f, a1 = 0.f, a2 = 0.f, a3 = 0.f;
        #pragma unroll
        for (int d = 0; d < FFF_LEVELS; d++) {
            const unsigned base = ((vf >> (FFF_LEVELS - d)) - 1u) * (unsigned)FFF_ROW4;
            const float4 wv = wo4[base + chunk];   // 12 independent gathers
            const float ad = ap[d];                // broadcast (sequential lines)
            a0 = fmaf(ad, wv.x, a0);
            a1 = fmaf(ad, wv.y, a1);
            a2 = fmaf(ad, wv.z, a2);
            a3 = fmaf(ad, wv.w, a3);
        }

        reinterpret_cast<float4*>(out)[(size_t)tok * FFF_ROW4 + chunk] =
            make_float4(a0, a1, a2, a3);
    }
}

extern "C" void kernel_launch(void* const* d_in, const int* in_sizes, int n_in,
                              void* d_out, int out_size) {
    const float* x     = (const float*)d_in[0];
    const float* w_in  = (const float*)d_in[1];
    const float* w_out = (const float*)d_in[2];
    float* out = (float*)d_out;

    // k1: transpose w_out into node-major scratch.
    {
        dim3 block(32, 8);
        dim3 grid((FFF_NODES + 31) / 32, FFF_D / 32);
        fff_transpose_wout<<<grid, block>>>(w_out);
    }

    // k2: decision walk — one warp per token, 8 warps per 256-thread block.
    {
        fff_decide_kernel<<<FFF_B / 8, 256>>>(x, w_in);
    }

    // k3: chunk-partitioned accumulation — 6 groups x 64 blocks.
    {
        fff_accum_chunked<<<ACC_GROUPS * ACC_BLOCKS_PER_GROUP, 256>>>(out);
    }
}

// round 15
// speedup vs baseline: 1.3245x; 1.2448x over previous
#include <cuda_runtime.h>

// FFF (fast feedforward) sparse tree-walk, round 15 (R14 resubmit — infra fail).
// Best-known structure (R6 single kernel, 41.0us) + MIO diet.
// Inputs (metadata order):
//   d_in[0]: oldx  [8192, 768]  float32
//   d_in[1]: w_in  [4095, 768]  float32
//   d_in[2]: w_out [768, 4095]  float32
// Output: [8192, 768] float32
//
// Changes vs R6:
//  - phase-2 act broadcast hoisted: 12 shuffles once (was up to 72 in-loop),
//    12 row offsets precomputed once; gather loop is pure LDG+FFMA.
//  - launch_bounds(128,8): same 64-reg cap / warps-per-SM as (256,4) but
//    finer block quanta for wave balance.

#define FFF_B       8192
#define FFF_D       768
#define FFF_NODES   4095
#define FFF_DEPTH   11
#define FFF_LEVELS  (FFF_DEPTH + 1)      // 12 nodes on the path
#define FFF_ROW4    (FFF_D / 4)          // 192 float4 per 768-float row

// Transposed w_out scratch: [FFF_NODES, FFF_D] (node-major, coalesced rows).
__device__ float g_wout_t[(size_t)FFF_NODES * FFF_D];

// ---------------------------------------------------------------------------
// Tiled transpose: w_out [768, 4095] -> g_wout_t [4095, 768]
// ---------------------------------------------------------------------------
__global__ void fff_transpose_wout(const float* __restrict__ w_out) {
    __shared__ float tile[32][33];
    const int n0 = blockIdx.x * 32;   // node dim (4095)
    const int o0 = blockIdx.y * 32;   // output dim (768)

    const int n = n0 + threadIdx.x;
    #pragma unroll
    for (int j = 0; j < 4; j++) {
        const int o = o0 + threadIdx.y + j * 8;     // o < 768 always
        if (n < FFF_NODES) {
            tile[threadIdx.y + j * 8][threadIdx.x] = w_out[(size_t)o * FFF_NODES + n];
        }
    }
    __syncthreads();

    const int oo = o0 + threadIdx.x;                // always < 768
    #pragma unroll
    for (int j = 0; j < 4; j++) {
        const int nn = n0 + threadIdx.y + j * 8;
        if (nn < FFF_NODES) {
            g_wout_t[(size_t)nn * FFF_D + oo] = tile[threadIdx.x][threadIdx.y + j * 8];
        }
    }
}

__device__ __forceinline__ float fff_warp_sum(float v) {
    #pragma unroll
    for (int off = 16; off > 0; off >>= 1)
        v += __shfl_xor_sync(0xffffffffu, v, off);
    return v;
}

// ---------------------------------------------------------------------------
// Main kernel: one warp per token.
// Phase 1: serial decision walk; lane d keeps the level-d logit; one gelu.
// Phase 2: acts + row offsets materialized once, then 6 chunk iterations of
//          pure 12-gather + 48-FMA + 1 store (no MIO ops in the loop).
// ---------------------------------------------------------------------------
__global__ void __launch_bounds__(128, 8)
fff_walk_kernel(const float* __restrict__ x,
                const float* __restrict__ w_in,
                float* __restrict__ out) {
    const int warp = (int)((blockIdx.x * blockDim.x + threadIdx.x) >> 5);
    const int lane = threadIdx.x & 31;

    const float4* __restrict__ x4  = reinterpret_cast<const float4*>(x) + (size_t)warp * FFF_ROW4;
    const float4* __restrict__ wi4 = reinterpret_cast<const float4*>(w_in);
    const float4* __restrict__ wo4 = reinterpret_cast<const float4*>(g_wout_t);

    // Token's x row: 6 float4 per lane, lane-interleaved (coalesced).
    float4 xv[6];
    #pragma unroll
    for (int i = 0; i < 6; i++) xv[i] = x4[i * 32 + lane];

    // ---------------- Phase 1: serial decision walk ----------------
    float mylogit = 0.f;   // lane d holds the level-d logit
    unsigned cur = 0;
    #pragma unroll
    for (int d = 0; d < FFF_LEVELS; d++) {
        const float4* __restrict__ wr = wi4 + (size_t)cur * FFF_ROW4;
        float p0 = 0.f, p1 = 0.f, p2 = 0.f, p3 = 0.f;
        #pragma unroll
        for (int i = 0; i < 6; i += 2) {
            const float4 a = wr[i * 32 + lane];
            const float4 b = wr[(i + 1) * 32 + lane];
            p0 = fmaf(a.x, xv[i].x, p0);
            p1 = fmaf(a.y, xv[i].y, p1);
            p2 = fmaf(a.z, xv[i].z, p2);
            p3 = fmaf(a.w, xv[i].w, p3);
            p0 = fmaf(b.x, xv[i + 1].x, p0);
            p1 = fmaf(b.y, xv[i + 1].y, p1);
            p2 = fmaf(b.z, xv[i + 1].z, p2);
            p3 = fmaf(b.w, xv[i + 1].w, p3);
        }
        const float p = fff_warp_sum((p0 + p1) + (p2 + p3));
        if (lane == d) mylogit = p;        // predicated select
        cur = 2u * cur + 1u + (p > 0.0f ? 1u : 0u);
    }
    const unsigned vfinal = cur + 1u;      // level-12 virtual node + 1

    // ---- ONE exact-erf gelu (matches jax.nn.gelu approximate=False) ----
    const float myact = 0.5f * mylogit *
                        (1.0f + erff(mylogit * 0.70710678118654752440f));

    // ---- Materialize per-level acts + row offsets ONCE (xv is dead now) ----
    float    acts[FFF_LEVELS];
    unsigned offs[FFF_LEVELS];
    #pragma unroll
    for (int d = 0; d < FFF_LEVELS; d++) {
        acts[d] = __shfl_sync(0xffffffffu, myact, d);
        offs[d] = ((vfinal >> (FFF_LEVELS - d)) - 1u) * (unsigned)FFF_ROW4;
    }

    // ---------------- Phase 2: pure gather + FMA loop ----------------
    float4* __restrict__ o4 = reinterpret_cast<float4*>(out) + (size_t)warp * FFF_ROW4;
    #pragma unroll
    for (int i = 0; i < 6; i++) {
        const unsigned chunk = (unsigned)(i * 32 + lane);
        float a0 = 0.f, a1 = 0.f, a2 = 0.f, a3 = 0.f;
        #pragma unroll
        for (int d = 0; d < FFF_LEVELS; d++) {
            const float4 w = wo4[offs[d] + chunk];   // 12 independent gathers
            a0 = fmaf(acts[d], w.x, a0);
            a1 = fmaf(acts[d], w.y, a1);
            a2 = fmaf(acts[d], w.z, a2);
            a3 = fmaf(acts[d], w.w, a3);
        }
        o4[chunk] = make_float4(a0, a1, a2, a3);
    }
}

extern "C" void kernel_launch(void* const* d_in, const int* in_sizes, int n_in,
                              void* d_out, int out_size) {
    const float* x     = (const float*)d_in[0];
    const float* w_in  = (const float*)d_in[1];
    const float* w_out = (const float*)d_in[2];
    float* out = (float*)d_out;

    // 1) Transpose w_out into node-major scratch (coalesced both sides).
    {
        dim3 block(32, 8);
        dim3 grid((FFF_NODES + 31) / 32, FFF_D / 32);
        fff_transpose_wout<<<grid, block>>>(w_out);
    }

    // 2) Sparse tree walk: one warp per token, 4 warps per 128-thread block.
    {
        const int threads = 128;
        const int blocks = FFF_B / 4;     // 2048 blocks
        fff_walk_kernel<<<blocks, threads>>>(x, w_in, out);
    }
}